// round 10
// baseline (speedup 1.0000x reference)
#include <cuda_runtime.h>
#include <math.h>

#define NH   2048
#define TT   4096
#define WASH 200
#define TW   (TT - WASH)   // 3896
#define NBLK 128
#define RPB  16
#define RTHREADS 512
#define FSTRIDE 32
#define BCHUNKS 32

__device__ __align__(256) float  g_drive[(size_t)TT * NH];
__device__ __align__(256) float  g_X[(size_t)TT * NH];
__device__ __align__(256) float  g_A[(size_t)NH * NH];
__device__ __align__(256) double g_Ad[(size_t)NH * NH];
__device__ float  g_bpart[BCHUNKS][NH];
__device__ double g_bd[NH];
__device__ double g_y1[NH];
__device__ double g_w[NH];
__device__ __align__(256) unsigned g_flags[NBLK * FSTRIDE];

// ---------- drive = u @ W_in^T ----------
__global__ void drive_kernel(const float* __restrict__ u, const float* __restrict__ Win) {
    __shared__ float Wins[128][65];
    __shared__ float us[64];
    int tid = threadIdx.x;                 // 128
    int r0 = blockIdx.x * 128, t0 = blockIdx.y * 32;
    for (int idx = tid; idx < 128 * 64; idx += 128)
        Wins[idx >> 6][idx & 63] = Win[(size_t)(r0 + (idx >> 6)) * 64 + (idx & 63)];
    __syncthreads();
    for (int tt = 0; tt < 32; ++tt) {
        int t = t0 + tt;
        if (tid < 64) us[tid] = u[(size_t)t * 64 + tid];
        __syncthreads();
        float acc = 0.f;
#pragma unroll
        for (int i = 0; i < 64; ++i) acc += Wins[tid][i] * us[i];
        g_drive[(size_t)t * NH + r0 + tid] = acc;
        __syncthreads();
    }
}

__global__ void reset_flags() { g_flags[threadIdx.x * FSTRIDE] = 0u; }

// ---------- persistent recurrence: W in registers ----------
__global__ void __launch_bounds__(RTHREADS, 1) recur_kernel(const float* __restrict__ Wres) {
    __shared__ float4 xs4[NH / 4];          // 8 KB
    __shared__ float  spart[RPB][4];
    int tid = threadIdx.x;
    int bid = blockIdx.x;
    int r0  = bid * RPB;
    int rg  = tid >> 7;        // 0..3  (4 rows each)
    int ct  = tid & 127;       // 0..127 (16 cols each, strided)
    int w4  = (tid >> 5) & 3;  // warp-within-rowgroup
    int lane = tid & 31;

    // load this thread's W tile into registers: rows rg*4+i, float4-cols ct+128k
    float4 w[4][4];
#pragma unroll
    for (int i = 0; i < 4; ++i)
#pragma unroll
        for (int k = 0; k < 4; ++k)
            w[i][k] = *(const float4*)&Wres[(size_t)(r0 + rg * 4 + i) * NH + (ct + 128 * k) * 4];

    for (int t = 0; t < TT; ++t) {
        // stage x_{t-1}: one coalesced float4 per thread
        if (t == 0) xs4[tid] = make_float4(0.f, 0.f, 0.f, 0.f);
        else        xs4[tid] = ((const float4*)(g_X + (size_t)(t - 1) * NH))[tid];
        __syncthreads();

        float4 xv[4];
#pragma unroll
        for (int k = 0; k < 4; ++k) xv[k] = xs4[ct + 128 * k];

        float p[4];
#pragma unroll
        for (int i = 0; i < 4; ++i) {
            float acc = 0.f;
#pragma unroll
            for (int k = 0; k < 4; ++k)
                acc += w[i][k].x * xv[k].x + w[i][k].y * xv[k].y
                     + w[i][k].z * xv[k].z + w[i][k].w * xv[k].w;
            p[i] = acc;
        }
#pragma unroll
        for (int off = 16; off; off >>= 1)
#pragma unroll
            for (int i = 0; i < 4; ++i)
                p[i] += __shfl_xor_sync(0xffffffffu, p[i], off);
        if (lane == 0)
#pragma unroll
            for (int i = 0; i < 4; ++i) spart[rg * 4 + i][w4] = p[i];
        __syncthreads();

        if (tid < RPB) {
            float s = spart[tid][0] + spart[tid][1] + spart[tid][2] + spart[tid][3];
            g_X[(size_t)t * NH + r0 + tid] = tanhf(s + g_drive[(size_t)t * NH + r0 + tid]);
        }
        __syncthreads();
        if (tid == 0) {
            __threadfence();
            asm volatile("st.release.gpu.u32 [%0], %1;" ::
                         "l"(&g_flags[bid * FSTRIDE]), "r"((unsigned)(t + 1)) : "memory");
        }
        if (tid < NBLK) {
            unsigned v;
            const unsigned* f = &g_flags[tid * FSTRIDE];
            do {
                asm volatile("ld.acquire.gpu.u32 %0, [%1];" : "=r"(v) : "l"(f) : "memory");
            } while (v <= (unsigned)t);
        }
        __syncthreads();
    }
}

// ---------- A = Xw^T Xw, lower tiles ----------
__global__ void __launch_bounds__(256) gemmA_kernel() {
    if (blockIdx.x > blockIdx.y) return;
    __shared__ float As[8][128], Bs[8][128];
    int tid = threadIdx.x;
    int i0 = blockIdx.y * 128, j0 = blockIdx.x * 128;
    const float* M = g_X + (size_t)WASH * NH;
    int lk = tid >> 5, lc = (tid & 31) << 2;
    int ty = tid >> 4, tx = tid & 15;
    float acc[8][8];
#pragma unroll
    for (int r = 0; r < 8; ++r)
#pragma unroll
        for (int c = 0; c < 8; ++c) acc[r][c] = 0.f;
    for (int kt = 0; kt < TW / 8; ++kt) {
        int kr = kt * 8 + lk;
        *(float4*)&As[lk][lc] = *(const float4*)&M[(size_t)kr * NH + i0 + lc];
        *(float4*)&Bs[lk][lc] = *(const float4*)&M[(size_t)kr * NH + j0 + lc];
        __syncthreads();
#pragma unroll
        for (int kk = 0; kk < 8; ++kk) {
            float a[8], b[8];
            *(float4*)&a[0] = *(float4*)&As[kk][ty * 8];
            *(float4*)&a[4] = *(float4*)&As[kk][ty * 8 + 4];
            *(float4*)&b[0] = *(float4*)&Bs[kk][tx * 8];
            *(float4*)&b[4] = *(float4*)&Bs[kk][tx * 8 + 4];
#pragma unroll
            for (int r = 0; r < 8; ++r)
#pragma unroll
                for (int c = 0; c < 8; ++c) acc[r][c] += a[r] * b[c];
        }
        __syncthreads();
    }
#pragma unroll
    for (int r = 0; r < 8; ++r) {
        size_t gi = (size_t)(i0 + ty * 8 + r) * NH + j0 + tx * 8;
#pragma unroll
        for (int c = 0; c < 8; ++c) g_A[gi + c] = acc[r][c];
    }
}

__global__ void mirror_kernel() {
    int j = blockIdx.x * 16 + threadIdx.x, i = blockIdx.y * 16 + threadIdx.y;
    if (j > i) g_A[(size_t)i * NH + j] = g_A[(size_t)j * NH + i];
}

__global__ void castA_kernel() {
    size_t idx = (size_t)blockIdx.x * 1024 + threadIdx.x;
    double v = (double)g_A[idx];
    if ((idx / NH) == (idx % NH)) v += 1e-6;
    g_Ad[idx] = v;
}

// ---------- b = Xw^T yw, two-stage deterministic ----------
__global__ void bvec_part(const float* __restrict__ y) {
    int chunk = blockIdx.y;
    int i = blockIdx.x * 128 + threadIdx.x;
    int len = (TW + BCHUNKS - 1) / BCHUNKS;
    int t0 = chunk * len;
    int t1 = t0 + len; if (t1 > TW) t1 = TW;
    float acc = 0.f;
    for (int t = t0; t < t1; ++t)
        acc += g_X[(size_t)(WASH + t) * NH + i] * y[WASH + t];
    g_bpart[chunk][i] = acc;
}

__global__ void bvec_sum() {
    int i = blockIdx.x * 128 + threadIdx.x;
    double acc = 0.0;
#pragma unroll
    for (int c = 0; c < BCHUNKS; ++c) acc += (double)g_bpart[c][i];
    g_bd[i] = acc;
}

// ---------- fp64 blocked Cholesky ----------
__global__ void potf2_kernel(int k0) {
    __shared__ double s[64][65];
    int tid = threadIdx.x;   // 64
    for (int j = 0; j < 64; ++j) s[tid][j] = g_Ad[(size_t)(k0 + tid) * NH + k0 + j];
    __syncthreads();
    for (int j = 0; j < 64; ++j) {
        if (tid == j) s[j][j] = sqrt(s[j][j]);
        __syncthreads();
        if (tid > j) s[tid][j] /= s[j][j];
        __syncthreads();
        if (tid > j) {
            double f = s[tid][j];
            for (int m = j + 1; m <= tid; ++m) s[tid][m] -= f * s[m][j];
        }
        __syncthreads();
    }
    for (int j = 0; j <= tid; ++j) g_Ad[(size_t)(k0 + tid) * NH + k0 + j] = s[tid][j];
}

__global__ void trsm_kernel(int k0) {
    __shared__ double Lkk[64][65];
    for (int idx = threadIdx.x; idx < 4096; idx += 64)
        Lkk[idx >> 6][idx & 63] = g_Ad[(size_t)(k0 + (idx >> 6)) * NH + k0 + (idx & 63)];
    __syncthreads();
    int i = k0 + 64 + blockIdx.x * 64 + threadIdx.x;
    if (i >= NH) return;
    double* ar = &g_Ad[(size_t)i * NH + k0];
    double x[64];
    for (int j = 0; j < 64; ++j) {
        double v = ar[j];
        for (int m = 0; m < j; ++m) v -= x[m] * Lkk[j][m];
        x[j] = v / Lkk[j][j];
    }
    for (int j = 0; j < 64; ++j) ar[j] = x[j];
}

__global__ void __launch_bounds__(256) syrk_kernel(int k1, int k0) {
    int i0 = k1 + blockIdx.y * 32, j0 = k1 + blockIdx.x * 32;
    if (j0 > i0) return;
    __shared__ double Pi[32][65], Pj[32][65];
    int tid = threadIdx.x;
    for (int idx = tid; idx < 2048; idx += 256) {
        int r = idx >> 6, c = idx & 63;
        Pi[r][c] = g_Ad[(size_t)(i0 + r) * NH + k0 + c];
        Pj[r][c] = g_Ad[(size_t)(j0 + r) * NH + k0 + c];
    }
    __syncthreads();
    int ty = tid >> 4, tx = tid & 15;
    int ri = ty * 2, cj = tx * 2;
    double a00 = 0, a01 = 0, a10 = 0, a11 = 0;
#pragma unroll 8
    for (int k = 0; k < 64; ++k) {
        double p0 = Pi[ri][k], p1 = Pi[ri + 1][k];
        double q0 = Pj[cj][k], q1 = Pj[cj + 1][k];
        a00 += p0 * q0; a01 += p0 * q1; a10 += p1 * q0; a11 += p1 * q1;
    }
    g_Ad[(size_t)(i0 + ri) * NH + j0 + cj]         -= a00;
    g_Ad[(size_t)(i0 + ri) * NH + j0 + cj + 1]     -= a01;
    g_Ad[(size_t)(i0 + ri + 1) * NH + j0 + cj]     -= a10;
    g_Ad[(size_t)(i0 + ri + 1) * NH + j0 + cj + 1] -= a11;
}

// ---------- triangular solves ----------
__global__ void __launch_bounds__(1024) trisolve_fwd() {
    __shared__ double rs[NH];
    int tid = threadIdx.x;
    rs[tid] = g_bd[tid]; rs[tid + 1024] = g_bd[tid + 1024];
    __syncthreads();
    for (int kb = 0; kb < NH / 32; ++kb) {
        int base = kb * 32;
        if (tid < 32) {
            double lr[32];
#pragma unroll
            for (int j = 0; j < 32; ++j) lr[j] = g_Ad[(size_t)(base + tid) * NH + base + j];
            double r = rs[base + tid];
#pragma unroll
            for (int j = 0; j < 32; ++j) {
                double xj = __shfl_sync(0xffffffffu, r / lr[j], j);
                if (tid == j) rs[base + j] = xj;
                else if (tid > j) r -= lr[j] * xj;
            }
        }
        __syncthreads();
        for (int i = base + 32 + tid; i < NH; i += 1024) {
            const double* Lr = &g_Ad[(size_t)i * NH + base];
            double acc = 0.0;
#pragma unroll
            for (int j = 0; j < 32; ++j) acc += Lr[j] * rs[base + j];
            rs[i] -= acc;
        }
        __syncthreads();
    }
    g_y1[tid] = rs[tid]; g_y1[tid + 1024] = rs[tid + 1024];
}

__global__ void __launch_bounds__(1024) trisolve_bwd() {
    __shared__ double rs[NH];
    int tid = threadIdx.x;
    rs[tid] = g_y1[tid]; rs[tid + 1024] = g_y1[tid + 1024];
    __syncthreads();
    for (int kb = NH / 32 - 1; kb >= 0; --kb) {
        int base = kb * 32;
        if (tid < 32) {
            double lc[32];
#pragma unroll
            for (int j = 0; j < 32; ++j) lc[j] = g_Ad[(size_t)(base + j) * NH + base + tid];
            double r = rs[base + tid];
#pragma unroll
            for (int j = 31; j >= 0; --j) {
                double xj = __shfl_sync(0xffffffffu, r / lc[j], j);
                if (tid == j) rs[base + j] = xj;
                else if (tid < j) r -= lc[j] * xj;
            }
        }
        __syncthreads();
        for (int i = tid; i < base; i += 1024) {
            double acc = 0.0;
#pragma unroll
            for (int j = 0; j < 32; ++j) acc += g_Ad[(size_t)(base + j) * NH + i] * rs[base + j];
            rs[i] -= acc;
        }
        __syncthreads();
    }
    g_w[tid] = rs[tid]; g_w[tid + 1024] = rs[tid + 1024];
}

// ---------- yhat = Xw @ w ----------
__global__ void yhat_kernel(float* __restrict__ out) {
    int row = blockIdx.x * 8 + (threadIdx.x >> 5);
    int lane = threadIdx.x & 31;
    if (row >= TW) return;
    const float* xr = g_X + (size_t)(WASH + row) * NH;
    double acc = 0.0;
    for (int c = lane; c < NH; c += 32) acc += (double)xr[c] * g_w[c];
#pragma unroll
    for (int off = 16; off; off >>= 1) acc += __shfl_xor_sync(0xffffffffu, acc, off);
    if (lane == 0) out[row] = (float)acc;
}

extern "C" void kernel_launch(void* const* d_in, const int* in_sizes, int n_in,
                              void* d_out, int out_size) {
    const float* u    = (const float*)d_in[0];
    const float* y    = (const float*)d_in[1];
    const float* Win  = (const float*)d_in[2];
    const float* Wres = (const float*)d_in[3];
    float* out = (float*)d_out;

    drive_kernel<<<dim3(16, 128), 128>>>(u, Win);
    reset_flags<<<1, NBLK>>>();
    recur_kernel<<<NBLK, RTHREADS>>>(Wres);
    gemmA_kernel<<<dim3(16, 16), 256>>>();
    mirror_kernel<<<dim3(128, 128), dim3(16, 16)>>>();
    castA_kernel<<<4096, 1024>>>();
    bvec_part<<<dim3(16, BCHUNKS), 128>>>(y);
    bvec_sum<<<16, 128>>>();

    for (int k0 = 0; k0 < NH; k0 += 64) {
        potf2_kernel<<<1, 64>>>(k0);
        int k1 = k0 + 64;
        if (k1 < NH) {
            int nrows = NH - k1;
            trsm_kernel<<<(nrows + 63) / 64, 64>>>(k0);
            int nt = nrows / 32;
            syrk_kernel<<<dim3(nt, nt), 256>>>(k1, k0);
        }
    }
    trisolve_fwd<<<1, 1024>>>();
    trisolve_bwd<<<1, 1024>>>();
    yhat_kernel<<<(TW + 7) / 8, 256>>>(out);
}

// round 11
// speedup vs baseline: 1.3991x; 1.3991x over previous
#include <cuda_runtime.h>
#include <math.h>

#define NH   2048
#define TT   4096
#define WASH 200
#define TW   (TT - WASH)   // 3896
#define NBLK 128
#define RPB  16
#define FSTRIDE 32
#define BCHUNKS 32
#define RSMEM ((RPB*NH + NH) * 4)   // 139264 bytes

__device__ __align__(256) float  g_drive[(size_t)TT * NH];
__device__ __align__(256) float  g_X[(size_t)TT * NH];
__device__ __align__(256) float  g_A[(size_t)NH * NH];
__device__ __align__(256) double g_Ad[(size_t)NH * NH];
__device__ float  g_bpart[BCHUNKS][NH];
__device__ double g_bd[NH];
__device__ double g_y1[NH];
__device__ double g_w[NH];
__device__ __align__(256) unsigned g_flags[NBLK * FSTRIDE];

// ---------- drive = u @ W_in^T ----------
__global__ void drive_kernel(const float* __restrict__ u, const float* __restrict__ Win) {
    __shared__ float Wins[128][65];
    __shared__ float us[64];
    int tid = threadIdx.x;                 // 128
    int r0 = blockIdx.x * 128, t0 = blockIdx.y * 32;
    for (int idx = tid; idx < 128 * 64; idx += 128)
        Wins[idx >> 6][idx & 63] = Win[(size_t)(r0 + (idx >> 6)) * 64 + (idx & 63)];
    __syncthreads();
    for (int tt = 0; tt < 32; ++tt) {
        int t = t0 + tt;
        if (tid < 64) us[tid] = u[(size_t)t * 64 + tid];
        __syncthreads();
        float acc = 0.f;
#pragma unroll
        for (int i = 0; i < 64; ++i) acc += Wins[tid][i] * us[i];
        g_drive[(size_t)t * NH + r0 + tid] = acc;
        __syncthreads();
    }
}

__global__ void reset_flags() { g_flags[threadIdx.x * FSTRIDE] = 0u; }

// ---------- persistent recurrence: smem W + overlapped producer/consumer staging ----------
__global__ void __launch_bounds__(256, 1) recur_kernel(const float* __restrict__ Wres) {
    extern __shared__ float sh[];
    float* Ws = sh;                  // 128 KB: this block's 16 rows of W
    float* xs = sh + RPB * NH;       // 8 KB: x_{t-1}
    int tid = threadIdx.x, bid = blockIdx.x, r0 = bid * RPB;
    const float4* Wg = (const float4*)(Wres + (size_t)r0 * NH);
    float4* Ws4 = (float4*)Ws;
    for (int i = tid; i < RPB * NH / 4; i += 256) Ws4[i] = Wg[i];
    int row = tid >> 4, sub = tid & 15;
    int wid = tid >> 5, lane = tid & 31;
    const float4* wr = (const float4*)(Ws + (size_t)row * NH);
    float4* xs4 = (float4*)xs;
    for (int i = tid; i < NH / 4; i += 256) xs4[i] = make_float4(0.f, 0.f, 0.f, 0.f);
    __syncthreads();

    for (int t = 0; t < TT; ++t) {
        // prefetch drive (needed only after compute)
        float dv = 0.f;
        if (sub == 0) dv = g_drive[(size_t)t * NH + r0 + row];

        // matvec: 16 threads per row, 32 float4 each
        float acc = 0.f;
#pragma unroll
        for (int j = 0; j < 32; ++j) {
            int c = sub + (j << 4);
            float4 w = wr[c], xv = xs4[c];
            acc += w.x * xv.x + w.y * xv.y + w.z * xv.z + w.w * xv.w;
        }
#pragma unroll
        for (int off = 8; off; off >>= 1) acc += __shfl_xor_sync(0xffffffffu, acc, off, 16);
        if (sub == 0)
            g_X[(size_t)t * NH + r0 + row] = tanhf(acc + dv);

        __syncthreads();   // all xs reads done; all 16 stores issued
        if (tid == 0) {
            __threadfence();
            asm volatile("st.release.gpu.u32 [%0], %1;" ::
                         "l"(&g_flags[bid * FSTRIDE]), "r"((unsigned)(t + 1)) : "memory");
        }
        if (t + 1 < TT) {
            // warp w consumes producers [16w, 16w+16): poll, then load 256 floats
            if (lane < 16) {
                int p = (wid << 4) + lane;
                unsigned v;
                const unsigned* f = &g_flags[p * FSTRIDE];
                do {
                    asm volatile("ld.acquire.gpu.u32 %0, [%1];" : "=r"(v) : "l"(f) : "memory");
                } while (v < (unsigned)(t + 1));
            }
            __syncwarp();
            const float4* xrow = (const float4*)(g_X + (size_t)t * NH);
            int ix = (wid << 6) + (lane << 1);
            xs4[ix]     = xrow[ix];
            xs4[ix + 1] = xrow[ix + 1];
            __syncthreads();
        }
    }
}

// ---------- A = Xw^T Xw, lower tiles ----------
__global__ void __launch_bounds__(256) gemmA_kernel() {
    if (blockIdx.x > blockIdx.y) return;
    __shared__ float As[8][128], Bs[8][128];
    int tid = threadIdx.x;
    int i0 = blockIdx.y * 128, j0 = blockIdx.x * 128;
    const float* M = g_X + (size_t)WASH * NH;
    int lk = tid >> 5, lc = (tid & 31) << 2;
    int ty = tid >> 4, tx = tid & 15;
    float acc[8][8];
#pragma unroll
    for (int r = 0; r < 8; ++r)
#pragma unroll
        for (int c = 0; c < 8; ++c) acc[r][c] = 0.f;
    for (int kt = 0; kt < TW / 8; ++kt) {
        int kr = kt * 8 + lk;
        *(float4*)&As[lk][lc] = *(const float4*)&M[(size_t)kr * NH + i0 + lc];
        *(float4*)&Bs[lk][lc] = *(const float4*)&M[(size_t)kr * NH + j0 + lc];
        __syncthreads();
#pragma unroll
        for (int kk = 0; kk < 8; ++kk) {
            float a[8], b[8];
            *(float4*)&a[0] = *(float4*)&As[kk][ty * 8];
            *(float4*)&a[4] = *(float4*)&As[kk][ty * 8 + 4];
            *(float4*)&b[0] = *(float4*)&Bs[kk][tx * 8];
            *(float4*)&b[4] = *(float4*)&Bs[kk][tx * 8 + 4];
#pragma unroll
            for (int r = 0; r < 8; ++r)
#pragma unroll
                for (int c = 0; c < 8; ++c) acc[r][c] += a[r] * b[c];
        }
        __syncthreads();
    }
#pragma unroll
    for (int r = 0; r < 8; ++r) {
        size_t gi = (size_t)(i0 + ty * 8 + r) * NH + j0 + tx * 8;
#pragma unroll
        for (int c = 0; c < 8; ++c) g_A[gi + c] = acc[r][c];
    }
}

__global__ void mirror_kernel() {
    int j = blockIdx.x * 16 + threadIdx.x, i = blockIdx.y * 16 + threadIdx.y;
    if (j > i) g_A[(size_t)i * NH + j] = g_A[(size_t)j * NH + i];
}

__global__ void castA_kernel() {
    size_t idx = (size_t)blockIdx.x * 1024 + threadIdx.x;
    double v = (double)g_A[idx];
    if ((idx / NH) == (idx % NH)) v += 1e-6;
    g_Ad[idx] = v;
}

// ---------- b = Xw^T yw, two-stage deterministic ----------
__global__ void bvec_part(const float* __restrict__ y) {
    int chunk = blockIdx.y;
    int i = blockIdx.x * 128 + threadIdx.x;
    int len = (TW + BCHUNKS - 1) / BCHUNKS;
    int t0 = chunk * len;
    int t1 = t0 + len; if (t1 > TW) t1 = TW;
    float acc = 0.f;
    for (int t = t0; t < t1; ++t)
        acc += g_X[(size_t)(WASH + t) * NH + i] * y[WASH + t];
    g_bpart[chunk][i] = acc;
}

__global__ void bvec_sum() {
    int i = blockIdx.x * 128 + threadIdx.x;
    double acc = 0.0;
#pragma unroll
    for (int c = 0; c < BCHUNKS; ++c) acc += (double)g_bpart[c][i];
    g_bd[i] = acc;
}

// ---------- fp64 blocked Cholesky ----------
__global__ void potf2_kernel(int k0) {
    __shared__ double s[64][65];
    int tid = threadIdx.x;   // 64
    for (int j = 0; j < 64; ++j) s[tid][j] = g_Ad[(size_t)(k0 + tid) * NH + k0 + j];
    __syncthreads();
    for (int j = 0; j < 64; ++j) {
        if (tid == j) s[j][j] = sqrt(s[j][j]);
        __syncthreads();
        if (tid > j) s[tid][j] /= s[j][j];
        __syncthreads();
        if (tid > j) {
            double f = s[tid][j];
            for (int m = j + 1; m <= tid; ++m) s[tid][m] -= f * s[m][j];
        }
        __syncthreads();
    }
    for (int j = 0; j <= tid; ++j) g_Ad[(size_t)(k0 + tid) * NH + k0 + j] = s[tid][j];
}

__global__ void trsm_kernel(int k0) {
    __shared__ double Lkk[64][65];
    for (int idx = threadIdx.x; idx < 4096; idx += 64)
        Lkk[idx >> 6][idx & 63] = g_Ad[(size_t)(k0 + (idx >> 6)) * NH + k0 + (idx & 63)];
    __syncthreads();
    int i = k0 + 64 + blockIdx.x * 64 + threadIdx.x;
    if (i >= NH) return;
    double* ar = &g_Ad[(size_t)i * NH + k0];
    double x[64];
    for (int j = 0; j < 64; ++j) {
        double v = ar[j];
        for (int m = 0; m < j; ++m) v -= x[m] * Lkk[j][m];
        x[j] = v / Lkk[j][j];
    }
    for (int j = 0; j < 64; ++j) ar[j] = x[j];
}

__global__ void __launch_bounds__(256) syrk_kernel(int k1, int k0) {
    int i0 = k1 + blockIdx.y * 32, j0 = k1 + blockIdx.x * 32;
    if (j0 > i0) return;
    __shared__ double Pi[32][65], Pj[32][65];
    int tid = threadIdx.x;
    for (int idx = tid; idx < 2048; idx += 256) {
        int r = idx >> 6, c = idx & 63;
        Pi[r][c] = g_Ad[(size_t)(i0 + r) * NH + k0 + c];
        Pj[r][c] = g_Ad[(size_t)(j0 + r) * NH + k0 + c];
    }
    __syncthreads();
    int ty = tid >> 4, tx = tid & 15;
    int ri = ty * 2, cj = tx * 2;
    double a00 = 0, a01 = 0, a10 = 0, a11 = 0;
#pragma unroll 8
    for (int k = 0; k < 64; ++k) {
        double p0 = Pi[ri][k], p1 = Pi[ri + 1][k];
        double q0 = Pj[cj][k], q1 = Pj[cj + 1][k];
        a00 += p0 * q0; a01 += p0 * q1; a10 += p1 * q0; a11 += p1 * q1;
    }
    g_Ad[(size_t)(i0 + ri) * NH + j0 + cj]         -= a00;
    g_Ad[(size_t)(i0 + ri) * NH + j0 + cj + 1]     -= a01;
    g_Ad[(size_t)(i0 + ri + 1) * NH + j0 + cj]     -= a10;
    g_Ad[(size_t)(i0 + ri + 1) * NH + j0 + cj + 1] -= a11;
}

// ---------- triangular solves ----------
__global__ void __launch_bounds__(1024) trisolve_fwd() {
    __shared__ double rs[NH];
    int tid = threadIdx.x;
    rs[tid] = g_bd[tid]; rs[tid + 1024] = g_bd[tid + 1024];
    __syncthreads();
    for (int kb = 0; kb < NH / 32; ++kb) {
        int base = kb * 32;
        if (tid < 32) {
            double lr[32];
#pragma unroll
            for (int j = 0; j < 32; ++j) lr[j] = g_Ad[(size_t)(base + tid) * NH + base + j];
            double r = rs[base + tid];
#pragma unroll
            for (int j = 0; j < 32; ++j) {
                double xj = __shfl_sync(0xffffffffu, r / lr[j], j);
                if (tid == j) rs[base + j] = xj;
                else if (tid > j) r -= lr[j] * xj;
            }
        }
        __syncthreads();
        for (int i = base + 32 + tid; i < NH; i += 1024) {
            const double* Lr = &g_Ad[(size_t)i * NH + base];
            double acc = 0.0;
#pragma unroll
            for (int j = 0; j < 32; ++j) acc += Lr[j] * rs[base + j];
            rs[i] -= acc;
        }
        __syncthreads();
    }
    g_y1[tid] = rs[tid]; g_y1[tid + 1024] = rs[tid + 1024];
}

__global__ void __launch_bounds__(1024) trisolve_bwd() {
    __shared__ double rs[NH];
    int tid = threadIdx.x;
    rs[tid] = g_y1[tid]; rs[tid + 1024] = g_y1[tid + 1024];
    __syncthreads();
    for (int kb = NH / 32 - 1; kb >= 0; --kb) {
        int base = kb * 32;
        if (tid < 32) {
            double lc[32];
#pragma unroll
            for (int j = 0; j < 32; ++j) lc[j] = g_Ad[(size_t)(base + j) * NH + base + tid];
            double r = rs[base + tid];
#pragma unroll
            for (int j = 31; j >= 0; --j) {
                double xj = __shfl_sync(0xffffffffu, r / lc[j], j);
                if (tid == j) rs[base + j] = xj;
                else if (tid < j) r -= lc[j] * xj;
            }
        }
        __syncthreads();
        for (int i = tid; i < base; i += 1024) {
            double acc = 0.0;
#pragma unroll
            for (int j = 0; j < 32; ++j) acc += g_Ad[(size_t)(base + j) * NH + i] * rs[base + j];
            rs[i] -= acc;
        }
        __syncthreads();
    }
    g_w[tid] = rs[tid]; g_w[tid + 1024] = rs[tid + 1024];
}

// ---------- yhat = Xw @ w ----------
__global__ void yhat_kernel(float* __restrict__ out) {
    int row = blockIdx.x * 8 + (threadIdx.x >> 5);
    int lane = threadIdx.x & 31;
    if (row >= TW) return;
    const float* xr = g_X + (size_t)(WASH + row) * NH;
    double acc = 0.0;
    for (int c = lane; c < NH; c += 32) acc += (double)xr[c] * g_w[c];
#pragma unroll
    for (int off = 16; off; off >>= 1) acc += __shfl_xor_sync(0xffffffffu, acc, off);
    if (lane == 0) out[row] = (float)acc;
}

extern "C" void kernel_launch(void* const* d_in, const int* in_sizes, int n_in,
                              void* d_out, int out_size) {
    const float* u    = (const float*)d_in[0];
    const float* y    = (const float*)d_in[1];
    const float* Win  = (const float*)d_in[2];
    const float* Wres = (const float*)d_in[3];
    float* out = (float*)d_out;

    static int smem_set = 0;
    if (!smem_set) {
        cudaFuncSetAttribute(recur_kernel, cudaFuncAttributeMaxDynamicSharedMemorySize, RSMEM);
        smem_set = 1;
    }

    drive_kernel<<<dim3(16, 128), 128>>>(u, Win);
    reset_flags<<<1, NBLK>>>();
    recur_kernel<<<NBLK, 256, RSMEM>>>(Wres);
    gemmA_kernel<<<dim3(16, 16), 256>>>();
    mirror_kernel<<<dim3(128, 128), dim3(16, 16)>>>();
    castA_kernel<<<4096, 1024>>>();
    bvec_part<<<dim3(16, BCHUNKS), 128>>>(y);
    bvec_sum<<<16, 128>>>();

    for (int k0 = 0; k0 < NH; k0 += 64) {
        potf2_kernel<<<1, 64>>>(k0);
        int k1 = k0 + 64;
        if (k1 < NH) {
            int nrows = NH - k1;
            trsm_kernel<<<(nrows + 63) / 64, 64>>>(k0);
            int nt = nrows / 32;
            syrk_kernel<<<dim3(nt, nt), 256>>>(k1, k0);
        }
    }
    trisolve_fwd<<<1, 1024>>>();
    trisolve_bwd<<<1, 1024>>>();
    yhat_kernel<<<(TW + 7) / 8, 256>>>(out);
}

// round 12
// speedup vs baseline: 1.5846x; 1.1326x over previous
#include <cuda_runtime.h>
#include <math.h>

#define NH   2048
#define TT   4096
#define WASH 200
#define TW   (TT - WASH)   // 3896
#define NBLK 128
#define RPB  16
#define FSTRIDE 32
#define BCHUNKS 32
#define RSMEM ((RPB*NH + NH) * 4)   // 139264 bytes

__device__ __align__(256) float  g_drive[(size_t)TT * NH];
__device__ __align__(256) float  g_X[(size_t)TT * NH];
__device__ __align__(256) float  g_A[(size_t)NH * NH];
__device__ __align__(256) double g_Ad[(size_t)NH * NH];
__device__ float  g_bpart[BCHUNKS][NH];
__device__ double g_bd[NH];
__device__ double g_y1[NH];
__device__ double g_w[NH];
__device__ __align__(256) unsigned g_flags[NBLK * FSTRIDE];

// ---------- drive = u @ W_in^T ----------
__global__ void drive_kernel(const float* __restrict__ u, const float* __restrict__ Win) {
    __shared__ float Wins[128][65];
    __shared__ float us[64];
    int tid = threadIdx.x;                 // 128
    int r0 = blockIdx.x * 128, t0 = blockIdx.y * 32;
    for (int idx = tid; idx < 128 * 64; idx += 128)
        Wins[idx >> 6][idx & 63] = Win[(size_t)(r0 + (idx >> 6)) * 64 + (idx & 63)];
    __syncthreads();
    for (int tt = 0; tt < 32; ++tt) {
        int t = t0 + tt;
        if (tid < 64) us[tid] = u[(size_t)t * 64 + tid];
        __syncthreads();
        float acc = 0.f;
#pragma unroll
        for (int i = 0; i < 64; ++i) acc += Wins[tid][i] * us[i];
        g_drive[(size_t)t * NH + r0 + tid] = acc;
        __syncthreads();
    }
}

__global__ void reset_flags() { g_flags[threadIdx.x * FSTRIDE] = 0u; }

// no-op: shifts recur_kernel into ncu's captured launch slot (-s 5 -c 1)
__global__ void dummy_kernel() {}

// ---------- persistent recurrence: 4 rows/thread, x-reuse, overlapped staging ----------
__global__ void __launch_bounds__(256, 1) recur_kernel(const float* __restrict__ Wres) {
    extern __shared__ float sh[];
    float* Ws = sh;                  // 128 KB: this block's 16 rows of W
    float* xs = sh + RPB * NH;       // 8 KB: x_{t-1}
    __shared__ float spart[RPB][2];
    int tid = threadIdx.x, bid = blockIdx.x, r0 = bid * RPB;

    const float4* Wg = (const float4*)(Wres + (size_t)r0 * NH);
    float4* Ws4 = (float4*)Ws;
    for (int i = tid; i < RPB * NH / 4; i += 256) Ws4[i] = Wg[i];

    int sub  = tid & 63;        // 0..63  (column group)
    int rg   = tid >> 6;        // 0..3   -> rows 4rg..4rg+3
    int wid  = tid >> 5, lane = tid & 31;
    int half = wid & 1;         // which 32-sub half this warp covers
    float4* xs4 = (float4*)xs;
    const float4* W0 = (const float4*)(Ws + (size_t)(4 * rg + 0) * NH);
    const float4* W1 = (const float4*)(Ws + (size_t)(4 * rg + 1) * NH);
    const float4* W2 = (const float4*)(Ws + (size_t)(4 * rg + 2) * NH);
    const float4* W3 = (const float4*)(Ws + (size_t)(4 * rg + 3) * NH);

    for (int i = tid; i < NH / 4; i += 256) xs4[i] = make_float4(0.f, 0.f, 0.f, 0.f);
    __syncthreads();

    for (int t = 0; t < TT; ++t) {
        float dv = 0.f;
        if (tid < RPB) dv = g_drive[(size_t)t * NH + r0 + tid];

        float a0 = 0.f, a1 = 0.f, a2 = 0.f, a3 = 0.f;
#pragma unroll
        for (int j = 0; j < 8; ++j) {
            int c = sub + (j << 6);
            float4 xv = xs4[c];
            float4 w0 = W0[c], w1 = W1[c], w2 = W2[c], w3 = W3[c];
            a0 += w0.x * xv.x + w0.y * xv.y + w0.z * xv.z + w0.w * xv.w;
            a1 += w1.x * xv.x + w1.y * xv.y + w1.z * xv.z + w1.w * xv.w;
            a2 += w2.x * xv.x + w2.y * xv.y + w2.z * xv.z + w2.w * xv.w;
            a3 += w3.x * xv.x + w3.y * xv.y + w3.z * xv.z + w3.w * xv.w;
        }
#pragma unroll
        for (int off = 16; off; off >>= 1) {
            a0 += __shfl_xor_sync(0xffffffffu, a0, off);
            a1 += __shfl_xor_sync(0xffffffffu, a1, off);
            a2 += __shfl_xor_sync(0xffffffffu, a2, off);
            a3 += __shfl_xor_sync(0xffffffffu, a3, off);
        }
        if (lane == 0) {
            spart[4 * rg + 0][half] = a0;
            spart[4 * rg + 1][half] = a1;
            spart[4 * rg + 2][half] = a2;
            spart[4 * rg + 3][half] = a3;
        }
        __syncthreads();   // xs reads done; spart complete

        if (tid < RPB) {
            float s = spart[tid][0] + spart[tid][1];
            g_X[(size_t)t * NH + r0 + tid] = tanhf(s + dv);
        }
        __syncthreads();   // STG issued before release (causality via bar + release)
        if (tid == 0)
            asm volatile("st.release.gpu.u32 [%0], %1;" ::
                         "l"(&g_flags[bid * FSTRIDE]), "r"((unsigned)(t + 1)) : "memory");

        if (t + 1 < TT) {
            // warp w consumes producers [16w, 16w+16): poll, then stage 256 floats
            if (lane < 16) {
                int p = (wid << 4) + lane;
                unsigned v;
                const unsigned* f = &g_flags[p * FSTRIDE];
                do {
                    asm volatile("ld.acquire.gpu.u32 %0, [%1];" : "=r"(v) : "l"(f) : "memory");
                } while (v < (unsigned)(t + 1));
            }
            __syncwarp();
            const float4* xrow = (const float4*)(g_X + (size_t)t * NH);
            int ix = (wid << 6) + (lane << 1);
            xs4[ix]     = xrow[ix];
            xs4[ix + 1] = xrow[ix + 1];
            __syncthreads();
        }
    }
}

// ---------- A = Xw^T Xw, lower tiles ----------
__global__ void __launch_bounds__(256) gemmA_kernel() {
    if (blockIdx.x > blockIdx.y) return;
    __shared__ float As[8][128], Bs[8][128];
    int tid = threadIdx.x;
    int i0 = blockIdx.y * 128, j0 = blockIdx.x * 128;
    const float* M = g_X + (size_t)WASH * NH;
    int lk = tid >> 5, lc = (tid & 31) << 2;
    int ty = tid >> 4, tx = tid & 15;
    float acc[8][8];
#pragma unroll
    for (int r = 0; r < 8; ++r)
#pragma unroll
        for (int c = 0; c < 8; ++c) acc[r][c] = 0.f;
    for (int kt = 0; kt < TW / 8; ++kt) {
        int kr = kt * 8 + lk;
        *(float4*)&As[lk][lc] = *(const float4*)&M[(size_t)kr * NH + i0 + lc];
        *(float4*)&Bs[lk][lc] = *(const float4*)&M[(size_t)kr * NH + j0 + lc];
        __syncthreads();
#pragma unroll
        for (int kk = 0; kk < 8; ++kk) {
            float a[8], b[8];
            *(float4*)&a[0] = *(float4*)&As[kk][ty * 8];
            *(float4*)&a[4] = *(float4*)&As[kk][ty * 8 + 4];
            *(float4*)&b[0] = *(float4*)&Bs[kk][tx * 8];
            *(float4*)&b[4] = *(float4*)&Bs[kk][tx * 8 + 4];
#pragma unroll
            for (int r = 0; r < 8; ++r)
#pragma unroll
                for (int c = 0; c < 8; ++c) acc[r][c] += a[r] * b[c];
        }
        __syncthreads();
    }
#pragma unroll
    for (int r = 0; r < 8; ++r) {
        size_t gi = (size_t)(i0 + ty * 8 + r) * NH + j0 + tx * 8;
#pragma unroll
        for (int c = 0; c < 8; ++c) g_A[gi + c] = acc[r][c];
    }
}

__global__ void mirror_kernel() {
    int j = blockIdx.x * 16 + threadIdx.x, i = blockIdx.y * 16 + threadIdx.y;
    if (j > i) g_A[(size_t)i * NH + j] = g_A[(size_t)j * NH + i];
}

__global__ void castA_kernel() {
    size_t idx = (size_t)blockIdx.x * 1024 + threadIdx.x;
    double v = (double)g_A[idx];
    if ((idx / NH) == (idx % NH)) v += 1e-6;
    g_Ad[idx] = v;
}

// ---------- b = Xw^T yw, two-stage deterministic ----------
__global__ void bvec_part(const float* __restrict__ y) {
    int chunk = blockIdx.y;
    int i = blockIdx.x * 128 + threadIdx.x;
    int len = (TW + BCHUNKS - 1) / BCHUNKS;
    int t0 = chunk * len;
    int t1 = t0 + len; if (t1 > TW) t1 = TW;
    float acc = 0.f;
    for (int t = t0; t < t1; ++t)
        acc += g_X[(size_t)(WASH + t) * NH + i] * y[WASH + t];
    g_bpart[chunk][i] = acc;
}

__global__ void bvec_sum() {
    int i = blockIdx.x * 128 + threadIdx.x;
    double acc = 0.0;
#pragma unroll
    for (int c = 0; c < BCHUNKS; ++c) acc += (double)g_bpart[c][i];
    g_bd[i] = acc;
}

// ---------- fp64 blocked Cholesky ----------
__global__ void potf2_kernel(int k0) {
    __shared__ double s[64][65];
    int tid = threadIdx.x;   // 64
    for (int j = 0; j < 64; ++j) s[tid][j] = g_Ad[(size_t)(k0 + tid) * NH + k0 + j];
    __syncthreads();
    for (int j = 0; j < 64; ++j) {
        if (tid == j) s[j][j] = sqrt(s[j][j]);
        __syncthreads();
        if (tid > j) s[tid][j] /= s[j][j];
        __syncthreads();
        if (tid > j) {
            double f = s[tid][j];
            for (int m = j + 1; m <= tid; ++m) s[tid][m] -= f * s[m][j];
        }
        __syncthreads();
    }
    for (int j = 0; j <= tid; ++j) g_Ad[(size_t)(k0 + tid) * NH + k0 + j] = s[tid][j];
}

__global__ void trsm_kernel(int k0) {
    __shared__ double Lkk[64][65];
    for (int idx = threadIdx.x; idx < 4096; idx += 64)
        Lkk[idx >> 6][idx & 63] = g_Ad[(size_t)(k0 + (idx >> 6)) * NH + k0 + (idx & 63)];
    __syncthreads();
    int i = k0 + 64 + blockIdx.x * 64 + threadIdx.x;
    if (i >= NH) return;
    double* ar = &g_Ad[(size_t)i * NH + k0];
    double x[64];
    for (int j = 0; j < 64; ++j) {
        double v = ar[j];
        for (int m = 0; m < j; ++m) v -= x[m] * Lkk[j][m];
        x[j] = v / Lkk[j][j];
    }
    for (int j = 0; j < 64; ++j) ar[j] = x[j];
}

__global__ void __launch_bounds__(256) syrk_kernel(int k1, int k0) {
    int i0 = k1 + blockIdx.y * 32, j0 = k1 + blockIdx.x * 32;
    if (j0 > i0) return;
    __shared__ double Pi[32][65], Pj[32][65];
    int tid = threadIdx.x;
    for (int idx = tid; idx < 2048; idx += 256) {
        int r = idx >> 6, c = idx & 63;
        Pi[r][c] = g_Ad[(size_t)(i0 + r) * NH + k0 + c];
        Pj[r][c] = g_Ad[(size_t)(j0 + r) * NH + k0 + c];
    }
    __syncthreads();
    int ty = tid >> 4, tx = tid & 15;
    int ri = ty * 2, cj = tx * 2;
    double a00 = 0, a01 = 0, a10 = 0, a11 = 0;
#pragma unroll 8
    for (int k = 0; k < 64; ++k) {
        double p0 = Pi[ri][k], p1 = Pi[ri + 1][k];
        double q0 = Pj[cj][k], q1 = Pj[cj + 1][k];
        a00 += p0 * q0; a01 += p0 * q1; a10 += p1 * q0; a11 += p1 * q1;
    }
    g_Ad[(size_t)(i0 + ri) * NH + j0 + cj]         -= a00;
    g_Ad[(size_t)(i0 + ri) * NH + j0 + cj + 1]     -= a01;
    g_Ad[(size_t)(i0 + ri + 1) * NH + j0 + cj]     -= a10;
    g_Ad[(size_t)(i0 + ri + 1) * NH + j0 + cj + 1] -= a11;
}

// ---------- triangular solves ----------
__global__ void __launch_bounds__(1024) trisolve_fwd() {
    __shared__ double rs[NH];
    int tid = threadIdx.x;
    rs[tid] = g_bd[tid]; rs[tid + 1024] = g_bd[tid + 1024];
    __syncthreads();
    for (int kb = 0; kb < NH / 32; ++kb) {
        int base = kb * 32;
        if (tid < 32) {
            double lr[32];
#pragma unroll
            for (int j = 0; j < 32; ++j) lr[j] = g_Ad[(size_t)(base + tid) * NH + base + j];
            double r = rs[base + tid];
#pragma unroll
            for (int j = 0; j < 32; ++j) {
                double xj = __shfl_sync(0xffffffffu, r / lr[j], j);
                if (tid == j) rs[base + j] = xj;
                else if (tid > j) r -= lr[j] * xj;
            }
        }
        __syncthreads();
        for (int i = base + 32 + tid; i < NH; i += 1024) {
            const double* Lr = &g_Ad[(size_t)i * NH + base];
            double acc = 0.0;
#pragma unroll
            for (int j = 0; j < 32; ++j) acc += Lr[j] * rs[base + j];
            rs[i] -= acc;
        }
        __syncthreads();
    }
    g_y1[tid] = rs[tid]; g_y1[tid + 1024] = rs[tid + 1024];
}

__global__ void __launch_bounds__(1024) trisolve_bwd() {
    __shared__ double rs[NH];
    int tid = threadIdx.x;
    rs[tid] = g_y1[tid]; rs[tid + 1024] = g_y1[tid + 1024];
    __syncthreads();
    for (int kb = NH / 32 - 1; kb >= 0; --kb) {
        int base = kb * 32;
        if (tid < 32) {
            double lc[32];
#pragma unroll
            for (int j = 0; j < 32; ++j) lc[j] = g_Ad[(size_t)(base + j) * NH + base + tid];
            double r = rs[base + tid];
#pragma unroll
            for (int j = 31; j >= 0; --j) {
                double xj = __shfl_sync(0xffffffffu, r / lc[j], j);
                if (tid == j) rs[base + j] = xj;
                else if (tid < j) r -= lc[j] * xj;
            }
        }
        __syncthreads();
        for (int i = tid; i < base; i += 1024) {
            double acc = 0.0;
#pragma unroll
            for (int j = 0; j < 32; ++j) acc += g_Ad[(size_t)(base + j) * NH + i] * rs[base + j];
            rs[i] -= acc;
        }
        __syncthreads();
    }
    g_w[tid] = rs[tid]; g_w[tid + 1024] = rs[tid + 1024];
}

// ---------- yhat = Xw @ w ----------
__global__ void yhat_kernel(float* __restrict__ out) {
    int row = blockIdx.x * 8 + (threadIdx.x >> 5);
    int lane = threadIdx.x & 31;
    if (row >= TW) return;
    const float* xr = g_X + (size_t)(WASH + row) * NH;
    double acc = 0.0;
    for (int c = lane; c < NH; c += 32) acc += (double)xr[c] * g_w[c];
#pragma unroll
    for (int off = 16; off; off >>= 1) acc += __shfl_xor_sync(0xffffffffu, acc, off);
    if (lane == 0) out[row] = (float)acc;
}

extern "C" void kernel_launch(void* const* d_in, const int* in_sizes, int n_in,
                              void* d_out, int out_size) {
    const float* u    = (const float*)d_in[0];
    const float* y    = (const float*)d_in[1];
    const float* Win  = (const float*)d_in[2];
    const float* Wres = (const float*)d_in[3];
    float* out = (float*)d_out;

    static int smem_set = 0;
    if (!smem_set) {
        cudaFuncSetAttribute(recur_kernel, cudaFuncAttributeMaxDynamicSharedMemorySize, RSMEM);
        smem_set = 1;
    }

    drive_kernel<<<dim3(16, 128), 128>>>(u, Win);
    reset_flags<<<1, NBLK>>>();
    dummy_kernel<<<1, 1>>>();                 // shifts recur into ncu's captured slot
    recur_kernel<<<NBLK, 256, RSMEM>>>(Wres);
    gemmA_kernel<<<dim3(16, 16), 256>>>();
    mirror_kernel<<<dim3(128, 128), dim3(16, 16)>>>();
    castA_kernel<<<4096, 1024>>>();
    bvec_part<<<dim3(16, BCHUNKS), 128>>>(y);
    bvec_sum<<<16, 128>>>();

    for (int k0 = 0; k0 < NH; k0 += 64) {
        potf2_kernel<<<1, 64>>>(k0);
        int k1 = k0 + 64;
        if (k1 < NH) {
            int nrows = NH - k1;
            trsm_kernel<<<(nrows + 63) / 64, 64>>>(k0);
            int nt = nrows / 32;
            syrk_kernel<<<dim3(nt, nt), 256>>>(k1, k0);
        }
    }
    trisolve_fwd<<<1, 1024>>>();
    trisolve_bwd<<<1, 1024>>>();
    yhat_kernel<<<(TW + 7) / 8, 256>>>(out);
}